// round 3
// baseline (speedup 1.0000x reference)
#include <cuda_runtime.h>
#include <cuda_bf16.h>
#include <cuda_pipeline.h>

#define NB_ACTIONS 64
#define NB_ELEMS 2080           // 64*65/2
#define EPS 1e-7f
#define WPB 4                   // warps per block
#define NBUF 2                  // double buffer

// Persistent warps, one batch row per warp-iteration.
// quad = d^T (L L^T) d = || L^T d ||^2 ; y_j = sum_{i>=j} d_i * L[i,j]
// Software pipeline: while computing row r from smem buffer b, cp.async
// streams row r+stride into buffer b^1 -> DRAM stays busy through compute.
__global__ __launch_bounds__(WPB * 32) void naf_kernel(
    const float* __restrict__ L_flat,
    const float* __restrict__ mu,
    const float* __restrict__ a,
    float* __restrict__ out,
    int batch, int total_warps)
{
    __shared__ __align__(16) float sL[WPB][NBUF][NB_ELEMS];

    const int wslot = threadIdx.x >> 5;
    const int lane  = threadIdx.x & 31;
    const int gw    = blockIdx.x * WPB + wslot;

    // ---- prefetch helper: 2080 floats = 520 float4, 17 cp.async per lane ----
    auto prefetch = [&](int buf, int row) {
        const float4* src = (const float4*)(L_flat + (size_t)row * NB_ELEMS);
        float4*       dst = (float4*)&sL[wslot][buf][0];
        #pragma unroll
        for (int it = 0; it < 16; ++it)
            __pipeline_memcpy_async(&dst[it * 32 + lane], &src[it * 32 + lane], 16);
        if (lane < 8)
            __pipeline_memcpy_async(&dst[512 + lane], &src[512 + lane], 16);
    };

    int row = gw;
    if (row < batch) prefetch(0, row);
    __pipeline_commit();                      // group for buf 0

    int buf = 0;
    while (row < batch) {
        const int nrow = row + total_warps;
        if (nrow < batch) prefetch(buf ^ 1, nrow);
        __pipeline_commit();                  // exactly one group per iteration

        // d = a - mu for THIS row (plain LDG, latency hides under the wait)
        const float* __restrict__ ar = a  + (size_t)row * NB_ACTIONS;
        const float* __restrict__ mr = mu + (size_t)row * NB_ACTIONS;
        const float d0 = ar[lane]      - mr[lane];
        const float d1 = ar[lane + 32] - mr[lane + 32];

        __pipeline_wait_prior(1);             // current buffer ready
        __syncwarp();

        // ---- y_j = sum_{i>=j} d_i * L[i,j] from smem ----
        const float* __restrict__ s = &sL[wslot][buf][0];
        float y0 = 0.0f;   // column j = lane
        float y1 = 0.0f;   // column j = lane + 32

        int off = 0;       // i*(i+1)/2 — compile-time after full unroll
        #pragma unroll
        for (int i = 0; i < NB_ACTIONS; ++i) {
            const float di = (i < 32) ? __shfl_sync(0xffffffffu, d0, i)
                                      : __shfl_sync(0xffffffffu, d1, i - 32);

            float v0 = (lane <= i) ? s[off + lane] : 0.0f;
            if (i < 32 && lane == i) v0 = __expf(v0) + EPS;   // diagonal
            y0 = fmaf(di, v0, y0);

            if (i >= 32) {
                float v1 = (lane + 32 <= i) ? s[off + 32 + lane] : 0.0f;
                if (lane + 32 == i) v1 = __expf(v1) + EPS;    // diagonal
                y1 = fmaf(di, v1, y1);
            }
            off += i + 1;
        }

        float q = fmaf(y0, y0, y1 * y1);
        #pragma unroll
        for (int sft = 16; sft > 0; sft >>= 1)
            q += __shfl_xor_sync(0xffffffffu, q, sft);

        if (lane == 0)
            out[row] = -0.5f * q;

        buf ^= 1;
        row = nrow;
    }
}

extern "C" void kernel_launch(void* const* d_in, const int* in_sizes, int n_in,
                              void* d_out, int out_size) {
    const float* L_flat = (const float*)d_in[0];
    const float* mu     = (const float*)d_in[1];
    const float* a      = (const float*)d_in[2];
    float* out          = (float*)d_out;

    const int batch = in_sizes[0] / NB_ELEMS;   // 32768

    // 3 blocks/SM (66.6 KB smem each) x 148 SMs
    int blocks = 3 * 148;
    const int max_blocks = (batch + WPB - 1) / WPB;
    if (blocks > max_blocks) blocks = max_blocks;
    const int total_warps = blocks * WPB;

    naf_kernel<<<blocks, WPB * 32>>>(L_flat, mu, a, out, batch, total_warps);
}

// round 4
// speedup vs baseline: 1.1234x; 1.1234x over previous
#include <cuda_runtime.h>
#include <cuda_bf16.h>
#include <cuda_pipeline.h>

#define NB_ACTIONS 64
#define NB_ELEMS 2080           // 64*65/2
#define EPS 1e-7f
#define WPB 4                   // warps per block
#define NSTAGE 4
#define STAGE_F 608             // floats per stage buffer (max chunk = 600)

// Chunk layout (row-aligned, float4-aligned):
//   c0: rows [ 0,32)  elems [   0, 528)  132 float4   base 0
//   c1: rows [32,47)  elems [ 528,1128)  150 float4   base 528
//   c2: rows [47,55)  elems [1128,1540)  103 float4   base 1128
//   c3: rows [55,64)  elems [1540,2080)  135 float4   base 1540

template<int N4>
__device__ __forceinline__ void pf(float4* __restrict__ dst,
                                   const float4* __restrict__ src, int lane) {
    #pragma unroll
    for (int k = 0; k < N4 / 32; ++k)
        __pipeline_memcpy_async(dst + k * 32 + lane, src + k * 32 + lane, 16);
    if ((N4 & 31) && lane < (N4 & 31))
        __pipeline_memcpy_async(dst + (N4 / 32) * 32 + lane,
                                src + (N4 / 32) * 32 + lane, 16);
}

// y_j += sum_{i in [ROW_BEG,ROW_END)} d_i * L[i,j] using smem chunk s (base BASE)
template<int ROW_BEG, int ROW_END, int BASE>
__device__ __forceinline__ void chunk_mac(const float* __restrict__ s,
                                          float d0, float d1, int lane,
                                          float& y0, float& y1) {
    int off = ROW_BEG * (ROW_BEG + 1) / 2 - BASE;
    #pragma unroll
    for (int i = ROW_BEG; i < ROW_END; ++i) {
        const float di = (i < 32) ? __shfl_sync(0xffffffffu, d0, i)
                                  : __shfl_sync(0xffffffffu, d1, i - 32);
        float v0 = (lane <= i) ? s[off + lane] : 0.0f;
        if (i < 32 && lane == i) v0 = __expf(v0) + EPS;       // diagonal
        y0 = fmaf(di, v0, y0);
        if (i >= 32) {
            float v1 = (lane + 32 <= i) ? s[off + 32 + lane] : 0.0f;
            if (lane + 32 == i) v1 = __expf(v1) + EPS;        // diagonal
            y1 = fmaf(di, v1, y1);
        }
        off += i + 1;
    }
}

__global__ __launch_bounds__(WPB * 32) void naf_kernel(
    const float* __restrict__ L_flat,
    const float* __restrict__ mu,
    const float* __restrict__ a,
    float* __restrict__ out,
    int batch, int total_warps)
{
    __shared__ __align__(16) float sL[WPB][NSTAGE][STAGE_F];

    const int wslot = threadIdx.x >> 5;
    const int lane  = threadIdx.x & 31;
    const int gw    = blockIdx.x * WPB + wslot;

    float4* const b0 = (float4*)&sL[wslot][0][0];
    float4* const b1 = (float4*)&sL[wslot][1][0];
    float4* const b2 = (float4*)&sL[wslot][2][0];
    float4* const b3 = (float4*)&sL[wslot][3][0];

    int row = gw;

    // ---- prologue: 4 groups (chunks of first row), empty groups if OOB ----
    if (row < batch) {
        const float4* src = (const float4*)(L_flat + (size_t)row * NB_ELEMS);
        pf<132>(b0, src,       lane); __pipeline_commit();
        pf<150>(b1, src + 132, lane); __pipeline_commit();
        pf<103>(b2, src + 282, lane); __pipeline_commit();
        pf<135>(b3, src + 385, lane); __pipeline_commit();
    } else {
        __pipeline_commit(); __pipeline_commit();
        __pipeline_commit(); __pipeline_commit();
    }

    float d0 = 0.0f, d1 = 0.0f;
    if (row < batch) {
        d0 = a[(size_t)row * NB_ACTIONS + lane]      - mu[(size_t)row * NB_ACTIONS + lane];
        d1 = a[(size_t)row * NB_ACTIONS + lane + 32] - mu[(size_t)row * NB_ACTIONS + lane + 32];
    }

    while (row < batch) {
        const int nrow = row + total_warps;
        const bool has_next = (nrow < batch);

        // prefetch next row's d early (consumed at loop end; 4 chunks to hide)
        float nd0 = 0.0f, nd1 = 0.0f;
        if (has_next) {
            nd0 = a[(size_t)nrow * NB_ACTIONS + lane]      - mu[(size_t)nrow * NB_ACTIONS + lane];
            nd1 = a[(size_t)nrow * NB_ACTIONS + lane + 32] - mu[(size_t)nrow * NB_ACTIONS + lane + 32];
        }
        const float4* nsrc = has_next
            ? (const float4*)(L_flat + (size_t)nrow * NB_ELEMS) : (const float4*)L_flat;

        float y0 = 0.0f, y1 = 0.0f;

        // chunk 0
        __pipeline_wait_prior(3); __syncwarp();
        chunk_mac<0, 32, 0>(&sL[wslot][0][0], d0, d1, lane, y0, y1);
        if (has_next) pf<132>(b0, nsrc, lane);
        __pipeline_commit();

        // chunk 1
        __pipeline_wait_prior(3); __syncwarp();
        chunk_mac<32, 47, 528>(&sL[wslot][1][0], d0, d1, lane, y0, y1);
        if (has_next) pf<150>(b1, nsrc + 132, lane);
        __pipeline_commit();

        // chunk 2
        __pipeline_wait_prior(3); __syncwarp();
        chunk_mac<47, 55, 1128>(&sL[wslot][2][0], d0, d1, lane, y0, y1);
        if (has_next) pf<103>(b2, nsrc + 282, lane);
        __pipeline_commit();

        // chunk 3
        __pipeline_wait_prior(3); __syncwarp();
        chunk_mac<55, 64, 1540>(&sL[wslot][3][0], d0, d1, lane, y0, y1);
        if (has_next) pf<135>(b3, nsrc + 385, lane);
        __pipeline_commit();

        // quad = sum_j y_j^2 ; warp butterfly reduction
        float q = fmaf(y0, y0, y1 * y1);
        #pragma unroll
        for (int sft = 16; sft > 0; sft >>= 1)
            q += __shfl_xor_sync(0xffffffffu, q, sft);
        if (lane == 0)
            out[row] = -0.5f * q;

        d0 = nd0; d1 = nd1;
        row = nrow;
    }
}

extern "C" void kernel_launch(void* const* d_in, const int* in_sizes, int n_in,
                              void* d_out, int out_size) {
    const float* L_flat = (const float*)d_in[0];
    const float* mu     = (const float*)d_in[1];
    const float* a      = (const float*)d_in[2];
    float* out          = (float*)d_out;

    const int batch = in_sizes[0] / NB_ELEMS;   // 32768

    // 5 blocks/SM (38.9 KB smem each) x 148 SMs, persistent warps
    int blocks = 5 * 148;
    const int max_blocks = (batch + WPB - 1) / WPB;
    if (blocks > max_blocks) blocks = max_blocks;
    const int total_warps = blocks * WPB;

    naf_kernel<<<blocks, WPB * 32>>>(L_flat, mu, a, out, batch, total_warps);
}

// round 5
// speedup vs baseline: 1.2495x; 1.1123x over previous
#include <cuda_runtime.h>
#include <cuda_bf16.h>
#include <cuda_pipeline.h>

#define NB_ACTIONS 64
#define NB_ELEMS 2080           // 64*65/2
#define EPS 1e-7f
#define WPB 4                   // warps per block
#define STAGE_F 656             // floats per stage buffer (max chunk = 648)

// Chunk layout (row-aligned, 4-row aligned, float4-aligned):
//   c0: rows [ 0,32)  elems [   0, 528)  132 f4  base    0
//   c1: rows [32,48)  elems [ 528,1176)  162 f4  base  528
//   c2: rows [48,56)  elems [1176,1596)  105 f4  base 1176
//   c3: rows [56,64)  elems [1596,2080)  121 f4  base 1596

template<int N4>
__device__ __forceinline__ void pf(float4* __restrict__ dst,
                                   const float4* __restrict__ src, int lane) {
    #pragma unroll
    for (int k = 0; k < N4 / 32; ++k)
        __pipeline_memcpy_async(dst + k * 32 + lane, src + k * 32 + lane, 16);
    if ((N4 & 31) && lane < (N4 & 31))
        __pipeline_memcpy_async(dst + (N4 / 32) * 32 + lane,
                                src + (N4 / 32) * 32 + lane, 16);
}

// y_j += sum_{i in [RB,RE)} d_i * Lraw[i,j]; d broadcast from smem as float4.
// Diagonal is accumulated RAW here and corrected outside the loop.
template<int RB, int RE, int BASE>
__device__ __forceinline__ void chunk_mac(const float* __restrict__ s,
                                          const float* __restrict__ sd,
                                          int lane, float& y0, float& y1) {
    int off = RB * (RB + 1) / 2 - BASE;
    #pragma unroll
    for (int g = RB; g < RE; g += 4) {
        const float4 dv = *(const float4*)(sd + g);   // uniform broadcast LDS.128
        #pragma unroll
        for (int k = 0; k < 4; ++k) {
            const int i = g + k;
            const float di = (k == 0) ? dv.x : (k == 1) ? dv.y : (k == 2) ? dv.z : dv.w;
            if (i < 32) {
                const float v0 = (lane <= i) ? s[off + lane] : 0.0f;
                y0 = fmaf(di, v0, y0);
            } else {
                y0 = fmaf(di, s[off + lane], y0);     // unpredicated: lane<32<=i
                const float v1 = (lane + 32 <= i) ? s[off + 32 + lane] : 0.0f;
                y1 = fmaf(di, v1, y1);
            }
            off += i + 1;
        }
    }
}

__global__ __launch_bounds__(WPB * 32, 5) void naf_kernel(
    const float* __restrict__ L_flat,
    const float* __restrict__ mu,
    const float* __restrict__ a,
    float* __restrict__ out,
    int batch, int total_warps)
{
    __shared__ __align__(16) float sL[WPB][4][STAGE_F];
    __shared__ __align__(16) float sD[WPB][NB_ACTIONS];

    const int wslot = threadIdx.x >> 5;
    const int lane  = threadIdx.x & 31;
    const int gw    = blockIdx.x * WPB + wslot;

    float4* const b0 = (float4*)&sL[wslot][0][0];
    float4* const b1 = (float4*)&sL[wslot][1][0];
    float4* const b2 = (float4*)&sL[wslot][2][0];
    float4* const b3 = (float4*)&sL[wslot][3][0];
    const float* const sd = &sD[wslot][0];

    int row = gw;

    // ---- prologue ----
    if (row < batch) {
        const float4* src = (const float4*)(L_flat + (size_t)row * NB_ELEMS);
        pf<132>(b0, src,       lane); __pipeline_commit();
        pf<162>(b1, src + 132, lane); __pipeline_commit();
        pf<105>(b2, src + 294, lane); __pipeline_commit();
        pf<121>(b3, src + 399, lane); __pipeline_commit();
    } else {
        __pipeline_commit(); __pipeline_commit();
        __pipeline_commit(); __pipeline_commit();
    }

    float d0 = 0.0f, d1 = 0.0f;
    if (row < batch) {
        d0 = a[(size_t)row * NB_ACTIONS + lane]      - mu[(size_t)row * NB_ACTIONS + lane];
        d1 = a[(size_t)row * NB_ACTIONS + lane + 32] - mu[(size_t)row * NB_ACTIONS + lane + 32];
        sD[wslot][lane]      = d0;
        sD[wslot][lane + 32] = d1;
    }
    __syncwarp();

    while (row < batch) {
        const int nrow = row + total_warps;
        const bool has_next = (nrow < batch);

        // prefetch next row's d early (4 chunk phases of slack to hide LDG)
        float nd0 = 0.0f, nd1 = 0.0f;
        if (has_next) {
            nd0 = a[(size_t)nrow * NB_ACTIONS + lane]      - mu[(size_t)nrow * NB_ACTIONS + lane];
            nd1 = a[(size_t)nrow * NB_ACTIONS + lane + 32] - mu[(size_t)nrow * NB_ACTIONS + lane + 32];
        }
        const float4* nsrc = has_next
            ? (const float4*)(L_flat + (size_t)nrow * NB_ELEMS) : (const float4*)L_flat;

        float y0 = 0.0f, y1 = 0.0f;
        float r0, r1 = 0.0f;
        const int j1 = lane + 32;

        // chunk 0: rows 0-31
        __pipeline_wait_prior(3); __syncwarp();
        chunk_mac<0, 32, 0>(&sL[wslot][0][0], sd, lane, y0, y1);
        r0 = sL[wslot][0][(lane * (lane + 3)) >> 1];          // raw diag j=lane
        if (has_next) pf<132>(b0, nsrc, lane);
        __pipeline_commit();

        // chunk 1: rows 32-47
        __pipeline_wait_prior(3); __syncwarp();
        chunk_mac<32, 48, 528>(&sL[wslot][1][0], sd, lane, y0, y1);
        if (lane < 16) r1 = sL[wslot][1][((j1 * (j1 + 3)) >> 1) - 528];
        if (has_next) pf<162>(b1, nsrc + 132, lane);
        __pipeline_commit();

        // chunk 2: rows 48-55
        __pipeline_wait_prior(3); __syncwarp();
        chunk_mac<48, 56, 1176>(&sL[wslot][2][0], sd, lane, y0, y1);
        if (lane >= 16 && lane < 24) r1 = sL[wslot][2][((j1 * (j1 + 3)) >> 1) - 1176];
        if (has_next) pf<105>(b2, nsrc + 294, lane);
        __pipeline_commit();

        // chunk 3: rows 56-63
        __pipeline_wait_prior(3); __syncwarp();
        chunk_mac<56, 64, 1596>(&sL[wslot][3][0], sd, lane, y0, y1);
        if (lane >= 24) r1 = sL[wslot][3][((j1 * (j1 + 3)) >> 1) - 1596];
        if (has_next) pf<121>(b3, nsrc + 399, lane);
        __pipeline_commit();

        // diagonal correction: replace raw L_jj by exp(L_jj)+eps in y_j
        y0 = fmaf(d0, (__expf(r0) + EPS) - r0, y0);
        y1 = fmaf(d1, (__expf(r1) + EPS) - r1, y1);

        // quad = sum_j y_j^2 ; warp butterfly reduction
        float q = fmaf(y0, y0, y1 * y1);
        #pragma unroll
        for (int sft = 16; sft > 0; sft >>= 1)
            q += __shfl_xor_sync(0xffffffffu, q, sft);
        if (lane == 0)
            out[row] = -0.5f * q;

        // publish next row's d (all this row's d reads are done)
        sD[wslot][lane]      = nd0;
        sD[wslot][lane + 32] = nd1;
        __syncwarp();

        d0 = nd0; d1 = nd1;
        row = nrow;
    }
}

extern "C" void kernel_launch(void* const* d_in, const int* in_sizes, int n_in,
                              void* d_out, int out_size) {
    const float* L_flat = (const float*)d_in[0];
    const float* mu     = (const float*)d_in[1];
    const float* a      = (const float*)d_in[2];
    float* out          = (float*)d_out;

    const int batch = in_sizes[0] / NB_ELEMS;   // 32768

    // 5 blocks/SM (43 KB smem each) x 148 SMs, persistent warps
    int blocks = 5 * 148;
    const int max_blocks = (batch + WPB - 1) / WPB;
    if (blocks > max_blocks) blocks = max_blocks;
    const int total_warps = blocks * WPB;

    naf_kernel<<<blocks, WPB * 32>>>(L_flat, mu, a, out, batch, total_warps);
}

// round 6
// speedup vs baseline: 1.2560x; 1.0052x over previous
#include <cuda_runtime.h>
#include <cuda_bf16.h>
#include <cuda_pipeline.h>

#define NB_ACTIONS 64
#define NB_ELEMS 2080           // 64*65/2
#define EPS 1e-7f
#define WPB 4                   // warps per block

// Whole packed-tril row lives contiguously in smem (2080 floats / warp).
// Pipeline chunks (row-aligned, float4-aligned element offsets):
//   c0: rows [ 0,32)  elems [   0, 528)  132 f4
//   c1: rows [32,48)  elems [ 528,1176)  162 f4
//   c2: rows [48,56)  elems [1176,1596)  105 f4
//   c3: rows [56,64)  elems [1596,2080)  121 f4

template<int N4>
__device__ __forceinline__ void pf(float4* __restrict__ dst,
                                   const float4* __restrict__ src, int lane) {
    #pragma unroll
    for (int k = 0; k < N4 / 32; ++k)
        __pipeline_memcpy_async(dst + k * 32 + lane, src + k * 32 + lane, 16);
    if ((N4 & 31) && lane < (N4 & 31))
        __pipeline_memcpy_async(dst + (N4 / 32) * 32 + lane,
                                src + (N4 / 32) * 32 + lane, 16);
}

// y_j += sum_{i in [RB,RE)} d_i * Lraw[i,j]; d broadcast via uniform LDS.128.
// Diagonal accumulated RAW, corrected once per row outside.
template<int RB, int RE>
__device__ __forceinline__ void chunk_mac(const float* __restrict__ s,
                                          const float* __restrict__ sd,
                                          int lane, float& y0, float& y1) {
    int off = RB * (RB + 1) / 2;
    #pragma unroll
    for (int g = RB; g < RE; g += 4) {
        const float4 dv = *(const float4*)(sd + g);
        #pragma unroll
        for (int k = 0; k < 4; ++k) {
            const int i = g + k;
            const float di = (k == 0) ? dv.x : (k == 1) ? dv.y : (k == 2) ? dv.z : dv.w;
            if (i < 32) {
                const float v0 = (lane <= i) ? s[off + lane] : 0.0f;
                y0 = fmaf(di, v0, y0);
            } else {
                y0 = fmaf(di, s[off + lane], y0);     // lane < 32 <= i: always valid
                const float v1 = (lane + 32 <= i) ? s[off + 32 + lane] : 0.0f;
                y1 = fmaf(di, v1, y1);
            }
            off += i + 1;
        }
    }
}

__global__ __launch_bounds__(WPB * 32, 6) void naf_kernel(
    const float* __restrict__ L_flat,
    const float* __restrict__ mu,
    const float* __restrict__ a,
    float* __restrict__ out,
    int batch, int total_warps)
{
    __shared__ __align__(16) float sL[WPB][NB_ELEMS];
    __shared__ __align__(16) float sD[WPB][NB_ACTIONS];

    const int wslot = threadIdx.x >> 5;
    const int lane  = threadIdx.x & 31;
    const int gw    = blockIdx.x * WPB + wslot;

    float* const sw = &sL[wslot][0];
    float4* const b0 = (float4*)(sw);
    float4* const b1 = (float4*)(sw + 528);
    float4* const b2 = (float4*)(sw + 1176);
    float4* const b3 = (float4*)(sw + 1596);
    const float* const sd = &sD[wslot][0];

    int row = gw;

    // ---- prologue: 4 groups = chunks of first row ----
    if (row < batch) {
        const float4* src = (const float4*)(L_flat + (size_t)row * NB_ELEMS);
        pf<132>(b0, src,       lane); __pipeline_commit();
        pf<162>(b1, src + 132, lane); __pipeline_commit();
        pf<105>(b2, src + 294, lane); __pipeline_commit();
        pf<121>(b3, src + 399, lane); __pipeline_commit();
    } else {
        __pipeline_commit(); __pipeline_commit();
        __pipeline_commit(); __pipeline_commit();
    }

    float d0 = 0.0f, d1 = 0.0f;
    if (row < batch) {
        d0 = a[(size_t)row * NB_ACTIONS + lane]      - mu[(size_t)row * NB_ACTIONS + lane];
        d1 = a[(size_t)row * NB_ACTIONS + lane + 32] - mu[(size_t)row * NB_ACTIONS + lane + 32];
        sD[wslot][lane]      = d0;
        sD[wslot][lane + 32] = d1;
    }
    __syncwarp();

    while (row < batch) {
        const int nrow = row + total_warps;
        const bool has_next = (nrow < batch);

        // prefetch next row's d early (4 chunk phases of slack to hide LDG)
        float nd0 = 0.0f, nd1 = 0.0f;
        if (has_next) {
            nd0 = a[(size_t)nrow * NB_ACTIONS + lane]      - mu[(size_t)nrow * NB_ACTIONS + lane];
            nd1 = a[(size_t)nrow * NB_ACTIONS + lane + 32] - mu[(size_t)nrow * NB_ACTIONS + lane + 32];
        }
        const float4* nsrc = has_next
            ? (const float4*)(L_flat + (size_t)nrow * NB_ELEMS) : (const float4*)L_flat;

        float y0 = 0.0f, y1 = 0.0f;
        float r0, r1 = 0.0f;
        const int j1 = lane + 32;

        // chunk 0: rows 0-31
        __pipeline_wait_prior(3); __syncwarp();
        chunk_mac<0, 32>(sw, sd, lane, y0, y1);
        r0 = sw[(lane * (lane + 3)) >> 1];                    // raw diag j=lane
        if (has_next) pf<132>(b0, nsrc, lane);
        __pipeline_commit();

        // chunk 1: rows 32-47
        __pipeline_wait_prior(3); __syncwarp();
        chunk_mac<32, 48>(sw, sd, lane, y0, y1);
        if (lane < 16) r1 = sw[(j1 * (j1 + 3)) >> 1];
        if (has_next) pf<162>(b1, nsrc + 132, lane);
        __pipeline_commit();

        // chunk 2: rows 48-55
        __pipeline_wait_prior(3); __syncwarp();
        chunk_mac<48, 56>(sw, sd, lane, y0, y1);
        if (lane >= 16 && lane < 24) r1 = sw[(j1 * (j1 + 3)) >> 1];
        if (has_next) pf<105>(b2, nsrc + 294, lane);
        __pipeline_commit();

        // chunk 3: rows 56-63
        __pipeline_wait_prior(3); __syncwarp();
        chunk_mac<56, 64>(sw, sd, lane, y0, y1);
        if (lane >= 24) r1 = sw[(j1 * (j1 + 3)) >> 1];
        if (has_next) pf<121>(b3, nsrc + 399, lane);
        __pipeline_commit();

        // diagonal correction: replace raw L_jj by exp(L_jj)+eps in y_j
        y0 = fmaf(d0, (__expf(r0) + EPS) - r0, y0);
        y1 = fmaf(d1, (__expf(r1) + EPS) - r1, y1);

        // quad = sum_j y_j^2 ; warp butterfly reduction
        float q = fmaf(y0, y0, y1 * y1);
        #pragma unroll
        for (int sft = 16; sft > 0; sft >>= 1)
            q += __shfl_xor_sync(0xffffffffu, q, sft);
        if (lane == 0)
            out[row] = -0.5f * q;

        // publish next row's d (all of this row's d reads are done)
        sD[wslot][lane]      = nd0;
        sD[wslot][lane + 32] = nd1;
        __syncwarp();

        d0 = nd0; d1 = nd1;
        row = nrow;
    }
}

extern "C" void kernel_launch(void* const* d_in, const int* in_sizes, int n_in,
                              void* d_out, int out_size) {
    const float* L_flat = (const float*)d_in[0];
    const float* mu     = (const float*)d_in[1];
    const float* a      = (const float*)d_in[2];
    float* out          = (float*)d_out;

    const int batch = in_sizes[0] / NB_ELEMS;   // 32768

    // 6 blocks/SM (34.3 KB smem each) x 148 SMs = 888 resident, SM-balanced
    int blocks = 6 * 148;
    const int max_blocks = (batch + WPB - 1) / WPB;
    if (blocks > max_blocks) blocks = max_blocks;
    const int total_warps = blocks * WPB;

    naf_kernel<<<blocks, WPB * 32>>>(L_flat, mu, a, out, batch, total_warps);
}